// round 9
// baseline (speedup 1.0000x reference)
#include <cuda_runtime.h>
#include <cuda_fp16.h>
#include <math.h>

// ---------------- problem constants ----------------
constexpr int B = 2, V = 3, G = 2, NH = 8, C = 128;
constexpr int CPG = C / G;       // 64
constexpr int CH  = C / NH;      // 16
constexpr int HPG = NH / G;      // 4
constexpr int Hq = 32, Wq = 32, M = Hq * Wq;   // 1024
constexpr int D = 4;
constexpr int Hk = Hq / 2, Wk = Wq * D;        // 16, 128
constexpr int NS = Hk * Wk;                    // 2048
constexpr int Hi = 64, Wi = 64;
constexpr int RH = Hq * 2 - 1;   // 63
constexpr int RW = Wq * D * 2 - 1; // 255
constexpr float SCALE = 0.25f;
constexpr float OFR = 5.0f;
constexpr float EPS = 1e-5f;
// rpe smem window: rows [i0-6, i0+38] (45), cols x in [-22, 281] -> c = x+22, 304 wide
constexpr int RPR = 45;
constexpr int RPW = 304;
constexpr int XOFF = 22;

// packed f32x2 helpers
#define FMA2(d, a, b, c) asm("fma.rn.f32x2 %0, %1, %2, %3;" : "=l"(d) : "l"(a), "l"(b), "l"(c))
#define MUL2(d, a, b)    asm("mul.rn.f32x2 %0, %1, %2;"     : "=l"(d) : "l"(a), "l"(b))
#define PACK2(d, lo, hi) asm("mov.b64 %0, {%1, %2};"        : "=l"(d) : "f"(lo), "f"(hi))
#define UNPACK2(lo, hi, v) asm("mov.b64 {%0, %1}, %2;"      : "=f"(lo), "=f"(hi) : "l"(v))

// ---------------- scratch ----------------
__device__ float g_rwo[V][B * G][NS][2];
__device__ float g_xs[V][B][C][NS];
__device__ float g_k[V][B][C][NS];
__device__ float g_v[V][B][C][NS];
__device__ float g_outcat[B][V * C][M];

// =====================================================================
// Kernel 1: offset net (unchanged — correct)
// =====================================================================
__global__ __launch_bounds__(256) void k_offset(
    const float* __restrict__ query,
    const float* __restrict__ refpts,
    const float* __restrict__ w1,
    const float* __restrict__ b1,
    const float* __restrict__ lng,
    const float* __restrict__ lnb,
    const float* __restrict__ w2)
{
    int pix = blockIdx.x * 256 + threadIdx.x;
    int bg = blockIdx.y, vi = blockIdx.z;
    int b = bg / G, g = bg % G;
    int y = pix >> 5, x = pix & 31;

    const float* W1 = w1 + vi * 256;
    const float* B1 = b1 + vi * 256;
    const float* LG = lng + vi * 256;
    const float* LB = lnb + vi * 256;
    const float* W2 = w2 + vi * 4 * 256;

    float s = 0.f, ss = 0.f;
    for (int c = 0; c < CPG; c++) {
        float qv = query[((b * C + g * CPG + c) * Hq + y) * Wq + x];
#pragma unroll
        for (int d = 0; d < 4; d++) {
            int cd = c * 4 + d;
            float hv = qv * W1[cd] + B1[cd];
            s += hv; ss += hv * hv;
        }
    }
    float mu  = s * (1.f / 256.f);
    float var = ss * (1.f / 256.f) - mu * mu;
    float rs  = rsqrtf(var + EPS);

    float po[4] = {0.f, 0.f, 0.f, 0.f};
    for (int c = 0; c < CPG; c++) {
        float qv = query[((b * C + g * CPG + c) * Hq + y) * Wq + x];
#pragma unroll
        for (int d = 0; d < 4; d++) {
            int cd = c * 4 + d;
            float hv = qv * W1[cd] + B1[cd];
            float hn = (hv - mu) * rs * LG[cd] + LB[cd];
            float ge = 0.5f * hn * (1.f + erff(hn * 0.70710678118654752f));
#pragma unroll
            for (int d2 = 0; d2 < 4; d2++)
                po[d2] += ge * W2[d2 * 256 + cd];
        }
    }

    int p = y & 1, hk = y >> 1;
    float scl = (p == 0) ? (OFR / (float)(Hk - 1)) : (OFR / (float)(Wk - 1));
#pragma unroll
    for (int d = 0; d < 4; d++) {
        int wk = x * 4 + d;
        float rv = refpts[(((b * V + vi) * Hk + hk) * Wk + wk) * 2 + (1 - p)];
        g_rwo[vi][bg][hk * Wk + wk][p] = tanhf(po[d]) * scl + rv;
    }
}

// =====================================================================
// Kernel 2: bilinear grid-sample of x (unchanged)
// =====================================================================
__global__ __launch_bounds__(256) void k_sample(const float* __restrict__ x)
{
    int cc = threadIdx.x & 63;
    int nsub = threadIdx.x >> 6;
    int n = blockIdx.x * 4 + nsub;
    int bg = blockIdx.y, vi = blockIdx.z;
    int b = bg / G, g = bg % G;

    float r0 = g_rwo[vi][bg][n][0];
    float r1 = g_rwo[vi][bg][n][1];
    float yp = (r0 + 1.f) * 0.5f * (float)(Hi - 1);
    float xp = (r1 + 1.f) * 0.5f * (float)(Wi - 1);
    float y0f = floorf(yp), x0f = floorf(xp);
    float fy = yp - y0f, fx = xp - x0f;
    int y0 = (int)y0f, x0 = (int)x0f;

    float wy0 = (y0     >= 0 && y0     <= Hi - 1) ? (1.f - fy) : 0.f;
    float wy1 = (y0 + 1 >= 0 && y0 + 1 <= Hi - 1) ? fy         : 0.f;
    float wx0 = (x0     >= 0 && x0     <= Wi - 1) ? (1.f - fx) : 0.f;
    float wx1 = (x0 + 1 >= 0 && x0 + 1 <= Wi - 1) ? fx         : 0.f;
    int iy0 = min(max(y0, 0), Hi - 1), iy1 = min(max(y0 + 1, 0), Hi - 1);
    int ix0 = min(max(x0, 0), Wi - 1), ix1 = min(max(x0 + 1, 0), Wi - 1);

    const float* img = x + (size_t)((b * V + vi) * C + g * CPG + cc) * (Hi * Wi);
    float val = wy0 * wx0 * img[iy0 * Wi + ix0]
              + wy0 * wx1 * img[iy0 * Wi + ix1]
              + wy1 * wx0 * img[iy1 * Wi + ix0]
              + wy1 * wx1 * img[iy1 * Wi + ix1];
    g_xs[vi][b][g * CPG + cc][n] = val;
}

// =====================================================================
// Kernel 3: K/V projection (unchanged)
// =====================================================================
__global__ __launch_bounds__(256) void k_proj(
    const float* __restrict__ kw, const float* __restrict__ kb,
    const float* __restrict__ vw, const float* __restrict__ vb)
{
    int n  = blockIdx.x * 256 + threadIdx.x;
    int o0 = blockIdx.y * 8;
    int z  = blockIdx.z;
    int kv = z & 1, b = (z >> 1) & 1, vi = z >> 2;
    const float* w    = kv ? vw : kw;
    const float* bias = kv ? vb : kb;

    __shared__ float sW[8][C];
    for (int idx = threadIdx.x; idx < 8 * C; idx += 256)
        sW[idx >> 7][idx & 127] = w[(o0 + (idx >> 7)) * C + (idx & 127)];
    __syncthreads();

    float acc[8];
#pragma unroll
    for (int oo = 0; oo < 8; oo++) acc[oo] = bias[o0 + oo];

    const float* xs = &g_xs[vi][b][0][0];
    for (int c = 0; c < C; c++) {
        float xv = xs[c * NS + n];
#pragma unroll
        for (int oo = 0; oo < 8; oo++) acc[oo] += sW[oo][c] * xv;
    }
    float* dst = kv ? &g_v[vi][b][0][0] : &g_k[vi][b][0][0];
#pragma unroll
    for (int oo = 0; oo < 8; oo++) dst[(o0 + oo) * NS + n] = acc[oo];
}

// =====================================================================
// Kernel 4: attention. 2-query tiling; float4-plane K/V smem (LDS.128);
// FFMA2 hot loops; ZERO-PADDED fp16 rpe window (no clamps, no validity
// selects — out-of-range entries read 0, matching reference semantics).
// =====================================================================
__global__ __launch_bounds__(256, 2) void k_attn(
    const float* __restrict__ query,
    const float* __restrict__ rpe_table)
{
    int warp = threadIdx.x >> 5, lane = threadIdx.x & 31, tid = threadIdx.x;
    int vi = blockIdx.z;
    int bh = blockIdx.y;
    int b = bh / NH, h = bh % NH;
    int g = h / HPG;
    int bg = b * G + g;

    int mp = blockIdx.x * 8 + warp;      // pair index 0..511
    int i0 = (mp >> 5) * 2;              // same for all warps in a block
    int j  = mp & 31;
    int m0 = i0 * 32 + j;
    int m1 = m0 + 32;

    // float4 channel planes: sK4[cp2][n] = (K[4cp2..4cp2+3][n])
    __shared__ float4 sK4[CH / 4][256];
    __shared__ float4 sV4[CH / 4][256];
    __shared__ float2 sR[256];
    __shared__ __half sRpe[RPR][RPW];    // zero-padded window

    int r_lo = i0 - 6;                   // may be negative; pad rows are zero

    const float* rpe = rpe_table + h * RH * RW;
    // fill zero-padded rpe window (once per block)
    for (int rr = warp; rr < RPR; rr += 8) {
        int trow = r_lo + rr;
        bool rok = (trow >= 0) && (trow < RH);
        const float* src = rpe + trow * RW;
        for (int c = lane; c < RPW; c += 32) {
            int xg = c - XOFF;
            float v = (rok && xg >= 0 && xg < RW) ? src[xg] : 0.f;
            sRpe[rr][c] = __float2half(v);
        }
    }

    // q packed as channel pairs, pre-scaled by SCALE
    unsigned long long qp0[CH / 2], qp1[CH / 2];
#pragma unroll
    for (int cp = 0; cp < CH / 2; cp++) {
        float a0 = query[(b * C + h * CH + 2 * cp) * M + m0] * SCALE;
        float b0 = query[(b * C + h * CH + 2 * cp + 1) * M + m0] * SCALE;
        float a1 = query[(b * C + h * CH + 2 * cp) * M + m1] * SCALE;
        float b1v = query[(b * C + h * CH + 2 * cp + 1) * M + m1] * SCALE;
        PACK2(qp0[cp], a0, b0);
        PACK2(qp1[cp], a1, b1v);
    }

    const float* kbase = &g_k[vi][b][h * CH][0];
    const float* vbase = &g_v[vi][b][h * CH][0];

    float ml0 = -1e30f, ll0 = 0.f, ml1 = -1e30f, ll1 = 0.f;
    unsigned long long ap0[CH / 2], ap1[CH / 2];
    unsigned long long zero2; { PACK2(zero2, 0.f, 0.f); }
#pragma unroll
    for (int cp = 0; cp < CH / 2; cp++) { ap0[cp] = zero2; ap1[cp] = zero2; }

    float ybase = 15.5f + (float)i0;
    float xbase = 63.5f + (127.0f / 31.0f) * (float)j;

    for (int t = 0; t < NS / 256; t++) {
        __syncthreads();
        // fill float4 planes: transpose 4 channel rows x 4 n
        {
            int idx = tid;                   // 256 items, 1 per thread
            int cp2 = idx >> 6, n4 = idx & 63;
            const float* kp = kbase + (4 * cp2) * NS + t * 256 + n4 * 4;
            float4 r0 = *(const float4*)(kp + 0 * NS);
            float4 r1 = *(const float4*)(kp + 1 * NS);
            float4 r2 = *(const float4*)(kp + 2 * NS);
            float4 r3 = *(const float4*)(kp + 3 * NS);
            float4* dst = &sK4[cp2][n4 * 4];
            dst[0] = make_float4(r0.x, r1.x, r2.x, r3.x);
            dst[1] = make_float4(r0.y, r1.y, r2.y, r3.y);
            dst[2] = make_float4(r0.z, r1.z, r2.z, r3.z);
            dst[3] = make_float4(r0.w, r1.w, r2.w, r3.w);
            const float* vp = vbase + (4 * cp2) * NS + t * 256 + n4 * 4;
            float4 s0 = *(const float4*)(vp + 0 * NS);
            float4 s1 = *(const float4*)(vp + 1 * NS);
            float4 s2 = *(const float4*)(vp + 2 * NS);
            float4 s3 = *(const float4*)(vp + 3 * NS);
            float4* dv = &sV4[cp2][n4 * 4];
            dv[0] = make_float4(s0.x, s1.x, s2.x, s3.x);
            dv[1] = make_float4(s0.y, s1.y, s2.y, s3.y);
            dv[2] = make_float4(s0.z, s1.z, s2.z, s3.z);
            dv[3] = make_float4(s0.w, s1.w, s2.w, s3.w);
        }
        sR[tid] = ((const float2*)&g_rwo[vi][bg][t * 256][0])[tid];
        __syncthreads();

#pragma unroll 1
        for (int ch = 0; ch < 8; ch++) {
            int nl = ch * 32 + lane;

            // QK: 4 LDS.128 + 16 FFMA2
            unsigned long long s0p = zero2, s1p = zero2;
#pragma unroll
            for (int cp2 = 0; cp2 < CH / 4; cp2++) {
                ulonglong2 kk = *(const ulonglong2*)&sK4[cp2][nl];
                FMA2(s0p, qp0[2 * cp2], kk.x, s0p);
                FMA2(s1p, qp1[2 * cp2], kk.x, s1p);
                FMA2(s0p, qp0[2 * cp2 + 1], kk.y, s0p);
                FMA2(s1p, qp1[2 * cp2 + 1], kk.y, s1p);
            }
            float s0a, s0b, s1a, s1b;
            UNPACK2(s0a, s0b, s0p);
            UNPACK2(s1a, s1b, s1p);
            float s0 = s0a + s0b, s1 = s1a + s1b;

            // --- bilinear rpe via zero-padded smem: no clamps, no selects ---
            float2 rv = sR[nl];
            float yp = ybase - 15.5f * rv.x;
            float xp = xbase - 63.5f * rv.y;
            float yf = floorf(yp), xf = floorf(xp);
            float fy = yp - yf, fx = xp - xf;
            int cy = (int)yf - r_lo;          // in [0, 42]
            int cx = (int)xf + XOFF;          // in [0, 297]

            const __half* r0p = &sRpe[cy][cx];
            float rc0 = (1.f - fx) * __half2float(r0p[0])   + fx * __half2float(r0p[1]);
            float rc1 = (1.f - fx) * __half2float(r0p[RPW]) + fx * __half2float(r0p[RPW + 1]);
            float rc2 = (1.f - fx) * __half2float(r0p[2 * RPW]) + fx * __half2float(r0p[2 * RPW + 1]);

            s0 += (1.f - fy) * rc0 + fy * rc1;
            s1 += (1.f - fy) * rc1 + fy * rc2;

            // --- per-lane online softmax ---
            if (s0 > ml0) {
                float sc = __expf(ml0 - s0);
                ll0 *= sc;
                unsigned long long scp; PACK2(scp, sc, sc);
#pragma unroll
                for (int cp = 0; cp < CH / 2; cp++) MUL2(ap0[cp], ap0[cp], scp);
                ml0 = s0;
            }
            float p0 = __expf(s0 - ml0);
            ll0 += p0;
            if (s1 > ml1) {
                float sc = __expf(ml1 - s1);
                ll1 *= sc;
                unsigned long long scp; PACK2(scp, sc, sc);
#pragma unroll
                for (int cp = 0; cp < CH / 2; cp++) MUL2(ap1[cp], ap1[cp], scp);
                ml1 = s1;
            }
            float p1 = __expf(s1 - ml1);
            ll1 += p1;

            unsigned long long p0p, p1p;
            PACK2(p0p, p0, p0);
            PACK2(p1p, p1, p1);
#pragma unroll
            for (int cp2 = 0; cp2 < CH / 4; cp2++) {
                ulonglong2 vv = *(const ulonglong2*)&sV4[cp2][nl];
                FMA2(ap0[2 * cp2], p0p, vv.x, ap0[2 * cp2]);
                FMA2(ap1[2 * cp2], p1p, vv.x, ap1[2 * cp2]);
                FMA2(ap0[2 * cp2 + 1], p0p, vv.y, ap0[2 * cp2 + 1]);
                FMA2(ap1[2 * cp2 + 1], p1p, vv.y, ap1[2 * cp2 + 1]);
            }
        }
    }

    // cross-lane reductions
    float gm0 = ml0, gm1 = ml1;
#pragma unroll
    for (int o = 16; o; o >>= 1) {
        gm0 = fmaxf(gm0, __shfl_xor_sync(0xffffffffu, gm0, o));
        gm1 = fmaxf(gm1, __shfl_xor_sync(0xffffffffu, gm1, o));
    }
    float f0 = __expf(ml0 - gm0), f1 = __expf(ml1 - gm1);
    float ls0 = ll0 * f0, ls1 = ll1 * f1;
#pragma unroll
    for (int o = 16; o; o >>= 1) {
        ls0 += __shfl_xor_sync(0xffffffffu, ls0, o);
        ls1 += __shfl_xor_sync(0xffffffffu, ls1, o);
    }
    float inv0 = 1.f / ls0, inv1 = 1.f / ls1;

#pragma unroll
    for (int cp = 0; cp < CH / 2; cp++) {
        float a0, b0, a1, b1v;
        UNPACK2(a0, b0, ap0[cp]);
        UNPACK2(a1, b1v, ap1[cp]);
        float o00 = a0 * f0, o01 = b0 * f0;
        float o10 = a1 * f1, o11 = b1v * f1;
#pragma unroll
        for (int q = 16; q; q >>= 1) {
            o00 += __shfl_xor_sync(0xffffffffu, o00, q);
            o01 += __shfl_xor_sync(0xffffffffu, o01, q);
            o10 += __shfl_xor_sync(0xffffffffu, o10, q);
            o11 += __shfl_xor_sync(0xffffffffu, o11, q);
        }
        if (lane == 0) {
            g_outcat[b][vi * C + h * CH + 2 * cp][m0]     = o00 * inv0;
            g_outcat[b][vi * C + h * CH + 2 * cp + 1][m0] = o01 * inv0;
            g_outcat[b][vi * C + h * CH + 2 * cp][m1]     = o10 * inv1;
            g_outcat[b][vi * C + h * CH + 2 * cp + 1][m1] = o11 * inv1;
        }
    }
}

// =====================================================================
// Kernel 5: output projection (unchanged)
// =====================================================================
__global__ __launch_bounds__(256) void k_out(
    const float* __restrict__ ow, const float* __restrict__ ob,
    float* __restrict__ out)
{
    int mm = blockIdx.x * 256 + threadIdx.x;
    int o0 = blockIdx.y * 8;
    int b  = blockIdx.z;

    __shared__ float sW[8][V * C];
    for (int idx = threadIdx.x; idx < 8 * V * C; idx += 256)
        sW[idx / (V * C)][idx % (V * C)] = ow[(o0 + idx / (V * C)) * (V * C) + (idx % (V * C))];
    __syncthreads();

    float acc[8];
#pragma unroll
    for (int oo = 0; oo < 8; oo++) acc[oo] = ob[o0 + oo];

    const float* src = &g_outcat[b][0][0];
    for (int c = 0; c < V * C; c++) {
        float xv = src[c * M + mm];
#pragma unroll
        for (int oo = 0; oo < 8; oo++) acc[oo] += sW[oo][c] * xv;
    }
#pragma unroll
    for (int oo = 0; oo < 8; oo++)
        out[(b * C + o0 + oo) * M + mm] = acc[oo];
}

// =====================================================================
extern "C" void kernel_launch(void* const* d_in, const int* in_sizes, int n_in,
                              void* d_out, int out_size)
{
    const float *x, *query, *refpts, *off_w1, *off_b1, *off_ln_g, *off_ln_b,
                *off_w2, *k_w, *k_b, *v_w, *v_b, *out_w, *out_b, *rpe;

    if (n_in >= 15 && in_sizes[0] == 3145728) {
        x        = (const float*)d_in[0];
        query    = (const float*)d_in[1];
        refpts   = (const float*)d_in[2];
        off_w1   = (const float*)d_in[3];
        off_b1   = (const float*)d_in[4];
        off_ln_g = (const float*)d_in[5];
        off_ln_b = (const float*)d_in[6];
        off_w2   = (const float*)d_in[7];
        k_w      = (const float*)d_in[8];
        k_b      = (const float*)d_in[9];
        v_w      = (const float*)d_in[10];
        v_b      = (const float*)d_in[11];
        out_w    = (const float*)d_in[12];
        out_b    = (const float*)d_in[13];
        rpe      = (const float*)d_in[14];
    } else {
        k_b      = (const float*)d_in[0];
        k_w      = (const float*)d_in[1];
        off_b1   = (const float*)d_in[2];
        off_ln_b = (const float*)d_in[3];
        off_ln_g = (const float*)d_in[4];
        off_w1   = (const float*)d_in[5];
        off_w2   = (const float*)d_in[6];
        out_b    = (const float*)d_in[7];
        out_w    = (const float*)d_in[8];
        query    = (const float*)d_in[9];
        refpts   = (const float*)d_in[10];
        rpe      = (const float*)d_in[11];
        v_b      = (const float*)d_in[12];
        v_w      = (const float*)d_in[13];
        x        = (const float*)d_in[14];
    }
    float* out = (float*)d_out;

    k_offset<<<dim3(M / 256, B * G, V), 256>>>(query, refpts, off_w1, off_b1,
                                               off_ln_g, off_ln_b, off_w2);
    k_sample<<<dim3(NS / 4, B * G, V), 256>>>(x);
    k_proj<<<dim3(NS / 256, C / 8, V * B * 2), 256>>>(k_w, k_b, v_w, v_b);
    k_attn<<<dim3(M / 2 / 8, B * NH, V), 256>>>(query, rpe);
    k_out<<<dim3(M / 256, C / 8, B), 256>>>(out_w, out_b, out);
}

// round 11
// speedup vs baseline: 1.6867x; 1.6867x over previous
#include <cuda_runtime.h>
#include <math.h>

// ---------------- problem constants ----------------
constexpr int B = 2, V = 3, G = 2, NH = 8, C = 128;
constexpr int CPG = C / G;       // 64
constexpr int CH  = C / NH;      // 16
constexpr int HPG = NH / G;      // 4
constexpr int Hq = 32, Wq = 32, M = Hq * Wq;   // 1024
constexpr int D = 4;
constexpr int Hk = Hq / 2, Wk = Wq * D;        // 16, 128
constexpr int NS = Hk * Wk;                    // 2048
constexpr int Hi = 64, Wi = 64;
constexpr int RH = Hq * 2 - 1;   // 63
constexpr int RW = Wq * D * 2 - 1; // 255
constexpr float SCALE = 0.25f;
constexpr float OFR = 5.0f;
constexpr float EPS = 1e-5f;
// zero-padded rpe window: rows [i0-6, i0+38] (45); cols x in [-22, 281] -> c=x+22
constexpr int RPR = 45;
constexpr int RPW = 304;
constexpr int XOFF = 22;

// packed f32x2 helpers
#define FMA2(d, a, b, c) asm("fma.rn.f32x2 %0, %1, %2, %3;" : "=l"(d) : "l"(a), "l"(b), "l"(c))
#define MUL2(d, a, b)    asm("mul.rn.f32x2 %0, %1, %2;"     : "=l"(d) : "l"(a), "l"(b))
#define PACK2(d, lo, hi) asm("mov.b64 %0, {%1, %2};"        : "=l"(d) : "f"(lo), "f"(hi))
#define UNPACK2(lo, hi, v) asm("mov.b64 {%0, %1}, %2;"      : "=f"(lo), "=f"(hi) : "l"(v))

// ---------------- scratch ----------------
__device__ float g_rwo[V][B * G][NS][2];
__device__ float g_xs[V][B][C][NS];
__device__ float g_k[V][B][C][NS];
__device__ float g_v[V][B][C][NS];
__device__ float g_outcat[B][V * C][M];

// =====================================================================
// Kernel 1: offset net (unchanged — correct)
// =====================================================================
__global__ __launch_bounds__(256) void k_offset(
    const float* __restrict__ query,
    const float* __restrict__ refpts,
    const float* __restrict__ w1,
    const float* __restrict__ b1,
    const float* __restrict__ lng,
    const float* __restrict__ lnb,
    const float* __restrict__ w2)
{
    int pix = blockIdx.x * 256 + threadIdx.x;
    int bg = blockIdx.y, vi = blockIdx.z;
    int b = bg / G, g = bg % G;
    int y = pix >> 5, x = pix & 31;

    const float* W1 = w1 + vi * 256;
    const float* B1 = b1 + vi * 256;
    const float* LG = lng + vi * 256;
    const float* LB = lnb + vi * 256;
    const float* W2 = w2 + vi * 4 * 256;

    float s = 0.f, ss = 0.f;
    for (int c = 0; c < CPG; c++) {
        float qv = query[((b * C + g * CPG + c) * Hq + y) * Wq + x];
#pragma unroll
        for (int d = 0; d < 4; d++) {
            int cd = c * 4 + d;
            float hv = qv * W1[cd] + B1[cd];
            s += hv; ss += hv * hv;
        }
    }
    float mu  = s * (1.f / 256.f);
    float var = ss * (1.f / 256.f) - mu * mu;
    float rs  = rsqrtf(var + EPS);

    float po[4] = {0.f, 0.f, 0.f, 0.f};
    for (int c = 0; c < CPG; c++) {
        float qv = query[((b * C + g * CPG + c) * Hq + y) * Wq + x];
#pragma unroll
        for (int d = 0; d < 4; d++) {
            int cd = c * 4 + d;
            float hv = qv * W1[cd] + B1[cd];
            float hn = (hv - mu) * rs * LG[cd] + LB[cd];
            float ge = 0.5f * hn * (1.f + erff(hn * 0.70710678118654752f));
#pragma unroll
            for (int d2 = 0; d2 < 4; d2++)
                po[d2] += ge * W2[d2 * 256 + cd];
        }
    }

    int p = y & 1, hk = y >> 1;
    float scl = (p == 0) ? (OFR / (float)(Hk - 1)) : (OFR / (float)(Wk - 1));
#pragma unroll
    for (int d = 0; d < 4; d++) {
        int wk = x * 4 + d;
        float rv = refpts[(((b * V + vi) * Hk + hk) * Wk + wk) * 2 + (1 - p)];
        g_rwo[vi][bg][hk * Wk + wk][p] = tanhf(po[d]) * scl + rv;
    }
}

// =====================================================================
// Kernel 2: bilinear grid-sample of x (unchanged)
// =====================================================================
__global__ __launch_bounds__(256) void k_sample(const float* __restrict__ x)
{
    int cc = threadIdx.x & 63;
    int nsub = threadIdx.x >> 6;
    int n = blockIdx.x * 4 + nsub;
    int bg = blockIdx.y, vi = blockIdx.z;
    int b = bg / G, g = bg % G;

    float r0 = g_rwo[vi][bg][n][0];
    float r1 = g_rwo[vi][bg][n][1];
    float yp = (r0 + 1.f) * 0.5f * (float)(Hi - 1);
    float xp = (r1 + 1.f) * 0.5f * (float)(Wi - 1);
    float y0f = floorf(yp), x0f = floorf(xp);
    float fy = yp - y0f, fx = xp - x0f;
    int y0 = (int)y0f, x0 = (int)x0f;

    float wy0 = (y0     >= 0 && y0     <= Hi - 1) ? (1.f - fy) : 0.f;
    float wy1 = (y0 + 1 >= 0 && y0 + 1 <= Hi - 1) ? fy         : 0.f;
    float wx0 = (x0     >= 0 && x0     <= Wi - 1) ? (1.f - fx) : 0.f;
    float wx1 = (x0 + 1 >= 0 && x0 + 1 <= Wi - 1) ? fx         : 0.f;
    int iy0 = min(max(y0, 0), Hi - 1), iy1 = min(max(y0 + 1, 0), Hi - 1);
    int ix0 = min(max(x0, 0), Wi - 1), ix1 = min(max(x0 + 1, 0), Wi - 1);

    const float* img = x + (size_t)((b * V + vi) * C + g * CPG + cc) * (Hi * Wi);
    float val = wy0 * wx0 * img[iy0 * Wi + ix0]
              + wy0 * wx1 * img[iy0 * Wi + ix1]
              + wy1 * wx0 * img[iy1 * Wi + ix0]
              + wy1 * wx1 * img[iy1 * Wi + ix1];
    g_xs[vi][b][g * CPG + cc][n] = val;
}

// =====================================================================
// Kernel 3: K/V projection (unchanged)
// =====================================================================
__global__ __launch_bounds__(256) void k_proj(
    const float* __restrict__ kw, const float* __restrict__ kb,
    const float* __restrict__ vw, const float* __restrict__ vb)
{
    int n  = blockIdx.x * 256 + threadIdx.x;
    int o0 = blockIdx.y * 8;
    int z  = blockIdx.z;
    int kv = z & 1, b = (z >> 1) & 1, vi = z >> 2;
    const float* w    = kv ? vw : kw;
    const float* bias = kv ? vb : kb;

    __shared__ float sW[8][C];
    for (int idx = threadIdx.x; idx < 8 * C; idx += 256)
        sW[idx >> 7][idx & 127] = w[(o0 + (idx >> 7)) * C + (idx & 127)];
    __syncthreads();

    float acc[8];
#pragma unroll
    for (int oo = 0; oo < 8; oo++) acc[oo] = bias[o0 + oo];

    const float* xs = &g_xs[vi][b][0][0];
    for (int c = 0; c < C; c++) {
        float xv = xs[c * NS + n];
#pragma unroll
        for (int oo = 0; oo < 8; oo++) acc[oo] += sW[oo][c] * xv;
    }
    float* dst = kv ? &g_v[vi][b][0][0] : &g_k[vi][b][0][0];
#pragma unroll
    for (int oo = 0; oo < 8; oo++) dst[(o0 + oo) * NS + n] = acc[oo];
}

// =====================================================================
// Kernel 4: attention. R8-proven structure (float2 interleaved K/V smem,
// lane-contiguous vectorized fill, 2-query tiling, FFMA2) + ZERO-PADDED
// fp32 rpe window (no clamps/selects/converts in the gather).
// =====================================================================
__global__ __launch_bounds__(256, 2) void k_attn(
    const float* __restrict__ query,
    const float* __restrict__ rpe_table)
{
    int warp = threadIdx.x >> 5, lane = threadIdx.x & 31, tid = threadIdx.x;
    int vi = blockIdx.z;
    int bh = blockIdx.y;
    int b = bh / NH, h = bh % NH;
    int g = h / HPG;
    int bg = b * G + g;

    int mp = blockIdx.x * 8 + warp;      // pair index 0..511
    int i0 = (mp >> 5) * 2;              // same for all warps in a block
    int j  = mp & 31;
    int m0 = i0 * 32 + j;
    int m1 = m0 + 32;

    // channel-pair interleaved: sK2[cp][n] = (K[2cp][n], K[2cp+1][n])
    __shared__ float2 sK2[CH / 2][256];
    __shared__ float2 sV2[CH / 2][256];
    __shared__ float sR0[256];
    __shared__ float sR1[256];
    __shared__ float sRpe[RPR][RPW];     // zero-padded fp32 window (~53.4 KB)

    int r_lo = i0 - 6;                   // may be negative; pad rows are zero

    const float* rpe = rpe_table + h * RH * RW;
    // fill zero-padded rpe window once per block (warp per row)
    for (int rr = warp; rr < RPR; rr += 8) {
        int trow = r_lo + rr;
        bool rok = (trow >= 0) && (trow < RH);
        const float* src = rpe + trow * RW;
        for (int c = lane; c < RPW; c += 32) {
            int xg = c - XOFF;
            sRpe[rr][c] = (rok && xg >= 0 && xg < RW) ? src[xg] : 0.f;
        }
    }

    // q packed as channel pairs, pre-scaled by SCALE
    unsigned long long qp0[CH / 2], qp1[CH / 2];
#pragma unroll
    for (int cp = 0; cp < CH / 2; cp++) {
        float a0 = query[(b * C + h * CH + 2 * cp) * M + m0] * SCALE;
        float b0 = query[(b * C + h * CH + 2 * cp + 1) * M + m0] * SCALE;
        float a1 = query[(b * C + h * CH + 2 * cp) * M + m1] * SCALE;
        float b1v = query[(b * C + h * CH + 2 * cp + 1) * M + m1] * SCALE;
        PACK2(qp0[cp], a0, b0);
        PACK2(qp1[cp], a1, b1v);
    }

    const float* kbase = &g_k[vi][b][h * CH][0];
    const float* vbase = &g_v[vi][b][h * CH][0];

    float ml0 = -1e30f, ll0 = 0.f, ml1 = -1e30f, ll1 = 0.f;
    unsigned long long ap0[CH / 2], ap1[CH / 2];
    unsigned long long zero2; { PACK2(zero2, 0.f, 0.f); }
#pragma unroll
    for (int cp = 0; cp < CH / 2; cp++) { ap0[cp] = zero2; ap1[cp] = zero2; }

    float ybase = 15.5f + (float)i0;
    float xbase = 63.5f + (127.0f / 31.0f) * (float)j;

    for (int t = 0; t < NS / 256; t++) {
        __syncthreads();
        // lane-contiguous vectorized interleaving fill (proven in R8)
        for (int idx = tid; idx < (CH / 2) * 64; idx += 256) {
            int cp = idx >> 6, n4 = idx & 63;
            float4 ka = ((const float4*)(kbase + (2 * cp) * NS + t * 256))[n4];
            float4 kb4 = ((const float4*)(kbase + (2 * cp + 1) * NS + t * 256))[n4];
            ((float4*)&sK2[cp][0])[2 * n4]     = make_float4(ka.x, kb4.x, ka.y, kb4.y);
            ((float4*)&sK2[cp][0])[2 * n4 + 1] = make_float4(ka.z, kb4.z, ka.w, kb4.w);
            float4 va = ((const float4*)(vbase + (2 * cp) * NS + t * 256))[n4];
            float4 vb4 = ((const float4*)(vbase + (2 * cp + 1) * NS + t * 256))[n4];
            ((float4*)&sV2[cp][0])[2 * n4]     = make_float4(va.x, vb4.x, va.y, vb4.y);
            ((float4*)&sV2[cp][0])[2 * n4 + 1] = make_float4(va.z, vb4.z, va.w, vb4.w);
        }
        {
            float2 rv = ((const float2*)&g_rwo[vi][bg][t * 256][0])[tid];
            sR0[tid] = rv.x;
            sR1[tid] = rv.y;
        }
        __syncthreads();

#pragma unroll 1
        for (int ch = 0; ch < 8; ch++) {
            int nl = ch * 32 + lane;

            // QK via packed channel pairs
            const unsigned long long* kc = (const unsigned long long*)&sK2[0][nl];
            unsigned long long s0p = zero2, s1p = zero2;
#pragma unroll
            for (int cp = 0; cp < CH / 2; cp++) {
                unsigned long long kk = kc[cp * 256];
                FMA2(s0p, qp0[cp], kk, s0p);
                FMA2(s1p, qp1[cp], kk, s1p);
            }
            float s0a, s0b, s1a, s1b;
            UNPACK2(s0a, s0b, s0p);
            UNPACK2(s1a, s1b, s1p);
            float s0 = s0a + s0b, s1 = s1a + s1b;

            // --- bilinear rpe via zero-padded smem: no clamps, no selects ---
            float r0v = sR0[nl], r1v = sR1[nl];
            float yp = ybase - 15.5f * r0v;
            float xp = xbase - 63.5f * r1v;
            float yf = floorf(yp), xf = floorf(xp);
            float fy = yp - yf, fx = xp - xf;
            int cy = (int)yf - r_lo;          // in [0, 42]
            int cx = (int)xf + XOFF;          // in [0, 297]

            const float* r0p = &sRpe[cy][cx];
            float rc0 = (1.f - fx) * r0p[0]       + fx * r0p[1];
            float rc1 = (1.f - fx) * r0p[RPW]     + fx * r0p[RPW + 1];
            float rc2 = (1.f - fx) * r0p[2 * RPW] + fx * r0p[2 * RPW + 1];

            s0 += (1.f - fy) * rc0 + fy * rc1;
            s1 += (1.f - fy) * rc1 + fy * rc2;

            // --- per-lane online softmax ---
            if (s0 > ml0) {
                float sc = __expf(ml0 - s0);
                ll0 *= sc;
                unsigned long long scp; PACK2(scp, sc, sc);
#pragma unroll
                for (int cp = 0; cp < CH / 2; cp++) MUL2(ap0[cp], ap0[cp], scp);
                ml0 = s0;
            }
            float p0 = __expf(s0 - ml0);
            ll0 += p0;
            if (s1 > ml1) {
                float sc = __expf(ml1 - s1);
                ll1 *= sc;
                unsigned long long scp; PACK2(scp, sc, sc);
#pragma unroll
                for (int cp = 0; cp < CH / 2; cp++) MUL2(ap1[cp], ap1[cp], scp);
                ml1 = s1;
            }
            float p1 = __expf(s1 - ml1);
            ll1 += p1;

            unsigned long long p0p, p1p;
            PACK2(p0p, p0, p0);
            PACK2(p1p, p1, p1);
            const unsigned long long* vc = (const unsigned long long*)&sV2[0][nl];
#pragma unroll
            for (int cp = 0; cp < CH / 2; cp++) {
                unsigned long long vvp = vc[cp * 256];
                FMA2(ap0[cp], p0p, vvp, ap0[cp]);
                FMA2(ap1[cp], p1p, vvp, ap1[cp]);
            }
        }
    }

    // cross-lane reductions
    float gm0 = ml0, gm1 = ml1;
#pragma unroll
    for (int o = 16; o; o >>= 1) {
        gm0 = fmaxf(gm0, __shfl_xor_sync(0xffffffffu, gm0, o));
        gm1 = fmaxf(gm1, __shfl_xor_sync(0xffffffffu, gm1, o));
    }
    float f0 = __expf(ml0 - gm0), f1 = __expf(ml1 - gm1);
    float ls0 = ll0 * f0, ls1 = ll1 * f1;
#pragma unroll
    for (int o = 16; o; o >>= 1) {
        ls0 += __shfl_xor_sync(0xffffffffu, ls0, o);
        ls1 += __shfl_xor_sync(0xffffffffu, ls1, o);
    }
    float inv0 = 1.f / ls0, inv1 = 1.f / ls1;

#pragma unroll
    for (int cp = 0; cp < CH / 2; cp++) {
        float a0, b0, a1, b1v;
        UNPACK2(a0, b0, ap0[cp]);
        UNPACK2(a1, b1v, ap1[cp]);
        float o00 = a0 * f0, o01 = b0 * f0;
        float o10 = a1 * f1, o11 = b1v * f1;
#pragma unroll
        for (int q = 16; q; q >>= 1) {
            o00 += __shfl_xor_sync(0xffffffffu, o00, q);
            o01 += __shfl_xor_sync(0xffffffffu, o01, q);
            o10 += __shfl_xor_sync(0xffffffffu, o10, q);
            o11 += __shfl_xor_sync(0xffffffffu, o11, q);
        }
        if (lane == 0) {
            g_outcat[b][vi * C + h * CH + 2 * cp][m0]     = o00 * inv0;
            g_outcat[b][vi * C + h * CH + 2 * cp + 1][m0] = o01 * inv0;
            g_outcat[b][vi * C + h * CH + 2 * cp][m1]     = o10 * inv1;
            g_outcat[b][vi * C + h * CH + 2 * cp + 1][m1] = o11 * inv1;
        }
    }
}

// =====================================================================
// Kernel 5: output projection (unchanged)
// =====================================================================
__global__ __launch_bounds__(256) void k_out(
    const float* __restrict__ ow, const float* __restrict__ ob,
    float* __restrict__ out)
{
    int mm = blockIdx.x * 256 + threadIdx.x;
    int o0 = blockIdx.y * 8;
    int b  = blockIdx.z;

    __shared__ float sW[8][V * C];
    for (int idx = threadIdx.x; idx < 8 * V * C; idx += 256)
        sW[idx / (V * C)][idx % (V * C)] = ow[(o0 + idx / (V * C)) * (V * C) + (idx % (V * C))];
    __syncthreads();

    float acc[8];
#pragma unroll
    for (int oo = 0; oo < 8; oo++) acc[oo] = ob[o0 + oo];

    const float* src = &g_outcat[b][0][0];
    for (int c = 0; c < V * C; c++) {
        float xv = src[c * M + mm];
#pragma unroll
        for (int oo = 0; oo < 8; oo++) acc[oo] += sW[oo][c] * xv;
    }
#pragma unroll
    for (int oo = 0; oo < 8; oo++)
        out[(b * C + o0 + oo) * M + mm] = acc[oo];
}

// =====================================================================
extern "C" void kernel_launch(void* const* d_in, const int* in_sizes, int n_in,
                              void* d_out, int out_size)
{
    const float *x, *query, *refpts, *off_w1, *off_b1, *off_ln_g, *off_ln_b,
                *off_w2, *k_w, *k_b, *v_w, *v_b, *out_w, *out_b, *rpe;

    if (n_in >= 15 && in_sizes[0] == 3145728) {
        x        = (const float*)d_in[0];
        query    = (const float*)d_in[1];
        refpts   = (const float*)d_in[2];
        off_w1   = (const float*)d_in[3];
        off_b1   = (const float*)d_in[4];
        off_ln_g = (const float*)d_in[5];
        off_ln_b = (const float*)d_in[6];
        off_w2   = (const float*)d_in[7];
        k_w      = (const float*)d_in[8];
        k_b      = (const float*)d_in[9];
        v_w      = (const float*)d_in[10];
        v_b      = (const float*)d_in[11];
        out_w    = (const float*)d_in[12];
        out_b    = (const float*)d_in[13];
        rpe      = (const float*)d_in[14];
    } else {
        k_b      = (const float*)d_in[0];
        k_w      = (const float*)d_in[1];
        off_b1   = (const float*)d_in[2];
        off_ln_b = (const float*)d_in[3];
        off_ln_g = (const float*)d_in[4];
        off_w1   = (const float*)d_in[5];
        off_w2   = (const float*)d_in[6];
        out_b    = (const float*)d_in[7];
        out_w    = (const float*)d_in[8];
        query    = (const float*)d_in[9];
        refpts   = (const float*)d_in[10];
        rpe      = (const float*)d_in[11];
        v_b      = (const float*)d_in[12];
        v_w      = (const float*)d_in[13];
        x        = (const float*)d_in[14];
    }
    float* out = (float*)d_out;

    k_offset<<<dim3(M / 256, B * G, V), 256>>>(query, refpts, off_w1, off_b1,
                                               off_ln_g, off_ln_b, off_w2);
    k_sample<<<dim3(NS / 4, B * G, V), 256>>>(x);
    k_proj<<<dim3(NS / 256, C / 8, V * B * 2), 256>>>(k_w, k_b, v_w, v_b);
    k_attn<<<dim3(M / 2 / 8, B * NH, V), 256>>>(query, rpe);
    k_out<<<dim3(M / 256, C / 8, B), 256>>>(out_w, out_b, out);
}

// round 14
// speedup vs baseline: 1.9016x; 1.1274x over previous
#include <cuda_runtime.h>
#include <cuda_fp16.h>
#include <math.h>

// ---------------- problem constants ----------------
constexpr int B = 2, V = 3, G = 2, NH = 8, C = 128;
constexpr int CPG = C / G;       // 64
constexpr int CH  = C / NH;      // 16
constexpr int HPG = NH / G;      // 4
constexpr int Hq = 32, Wq = 32, M = Hq * Wq;   // 1024
constexpr int D = 4;
constexpr int Hk = Hq / 2, Wk = Wq * D;        // 16, 128
constexpr int NS = Hk * Wk;                    // 2048
constexpr int Hi = 64, Wi = 64;
constexpr int RH = Hq * 2 - 1;   // 63
constexpr int RW = Wq * D * 2 - 1; // 255
constexpr float SCALE = 0.25f;
constexpr float OFR = 5.0f;
constexpr float EPS = 1e-5f;
// zero-padded rpe window: rows [i0-6, i0+38] (45); cols x in [-22, 281] -> c=x+22
constexpr int RPR = 45;
constexpr int RPW = 304;
constexpr int XOFF = 22;

// packed f32x2 helpers
#define FMA2(d, a, b, c) asm("fma.rn.f32x2 %0, %1, %2, %3;" : "=l"(d) : "l"(a), "l"(b), "l"(c))
#define MUL2(d, a, b)    asm("mul.rn.f32x2 %0, %1, %2;"     : "=l"(d) : "l"(a), "l"(b))
#define PACK2(d, lo, hi) asm("mov.b64 %0, {%1, %2};"        : "=l"(d) : "f"(lo), "f"(hi))
#define UNPACK2(lo, hi, v) asm("mov.b64 {%0, %1}, %2;"      : "=f"(lo), "=f"(hi) : "l"(v))

// ---------------- scratch ----------------
__device__ float g_rwo[V][B * G][NS][2];
__device__ float g_xs[V][B][C][NS];
__device__ float g_k[V][B][C][NS];
__device__ float g_v[V][B][C][NS];
__device__ float g_outcat[B][V * C][M];

// =====================================================================
// Kernel 1: offset net (unchanged — correct)
// =====================================================================
__global__ __launch_bounds__(256) void k_offset(
    const float* __restrict__ query,
    const float* __restrict__ refpts,
    const float* __restrict__ w1,
    const float* __restrict__ b1,
    const float* __restrict__ lng,
    const float* __restrict__ lnb,
    const float* __restrict__ w2)
{
    int pix = blockIdx.x * 256 + threadIdx.x;
    int bg = blockIdx.y, vi = blockIdx.z;
    int b = bg / G, g = bg % G;
    int y = pix >> 5, x = pix & 31;

    const float* W1 = w1 + vi * 256;
    const float* B1 = b1 + vi * 256;
    const float* LG = lng + vi * 256;
    const float* LB = lnb + vi * 256;
    const float* W2 = w2 + vi * 4 * 256;

    float s = 0.f, ss = 0.f;
    for (int c = 0; c < CPG; c++) {
        float qv = query[((b * C + g * CPG + c) * Hq + y) * Wq + x];
#pragma unroll
        for (int d = 0; d < 4; d++) {
            int cd = c * 4 + d;
            float hv = qv * W1[cd] + B1[cd];
            s += hv; ss += hv * hv;
        }
    }
    float mu  = s * (1.f / 256.f);
    float var = ss * (1.f / 256.f) - mu * mu;
    float rs  = rsqrtf(var + EPS);

    float po[4] = {0.f, 0.f, 0.f, 0.f};
    for (int c = 0; c < CPG; c++) {
        float qv = query[((b * C + g * CPG + c) * Hq + y) * Wq + x];
#pragma unroll
        for (int d = 0; d < 4; d++) {
            int cd = c * 4 + d;
            float hv = qv * W1[cd] + B1[cd];
            float hn = (hv - mu) * rs * LG[cd] + LB[cd];
            float ge = 0.5f * hn * (1.f + erff(hn * 0.70710678118654752f));
#pragma unroll
            for (int d2 = 0; d2 < 4; d2++)
                po[d2] += ge * W2[d2 * 256 + cd];
        }
    }

    int p = y & 1, hk = y >> 1;
    float scl = (p == 0) ? (OFR / (float)(Hk - 1)) : (OFR / (float)(Wk - 1));
#pragma unroll
    for (int d = 0; d < 4; d++) {
        int wk = x * 4 + d;
        float rv = refpts[(((b * V + vi) * Hk + hk) * Wk + wk) * 2 + (1 - p)];
        g_rwo[vi][bg][hk * Wk + wk][p] = tanhf(po[d]) * scl + rv;
    }
}

// =====================================================================
// Kernel 2: bilinear grid-sample of x (unchanged)
// =====================================================================
__global__ __launch_bounds__(256) void k_sample(const float* __restrict__ x)
{
    int cc = threadIdx.x & 63;
    int nsub = threadIdx.x >> 6;
    int n = blockIdx.x * 4 + nsub;
    int bg = blockIdx.y, vi = blockIdx.z;
    int b = bg / G, g = bg % G;

    float r0 = g_rwo[vi][bg][n][0];
    float r1 = g_rwo[vi][bg][n][1];
    float yp = (r0 + 1.f) * 0.5f * (float)(Hi - 1);
    float xp = (r1 + 1.f) * 0.5f * (float)(Wi - 1);
    float y0f = floorf(yp), x0f = floorf(xp);
    float fy = yp - y0f, fx = xp - x0f;
    int y0 = (int)y0f, x0 = (int)x0f;

    float wy0 = (y0     >= 0 && y0     <= Hi - 1) ? (1.f - fy) : 0.f;
    float wy1 = (y0 + 1 >= 0 && y0 + 1 <= Hi - 1) ? fy         : 0.f;
    float wx0 = (x0     >= 0 && x0     <= Wi - 1) ? (1.f - fx) : 0.f;
    float wx1 = (x0 + 1 >= 0 && x0 + 1 <= Wi - 1) ? fx         : 0.f;
    int iy0 = min(max(y0, 0), Hi - 1), iy1 = min(max(y0 + 1, 0), Hi - 1);
    int ix0 = min(max(x0, 0), Wi - 1), ix1 = min(max(x0 + 1, 0), Wi - 1);

    const float* img = x + (size_t)((b * V + vi) * C + g * CPG + cc) * (Hi * Wi);
    float val = wy0 * wx0 * img[iy0 * Wi + ix0]
              + wy0 * wx1 * img[iy0 * Wi + ix1]
              + wy1 * wx0 * img[iy1 * Wi + ix0]
              + wy1 * wx1 * img[iy1 * Wi + ix1];
    g_xs[vi][b][g * CPG + cc][n] = val;
}

// =====================================================================
// Kernel 3: K/V projection (unchanged)
// =====================================================================
__global__ __launch_bounds__(256) void k_proj(
    const float* __restrict__ kw, const float* __restrict__ kb,
    const float* __restrict__ vw, const float* __restrict__ vb)
{
    int n  = blockIdx.x * 256 + threadIdx.x;
    int o0 = blockIdx.y * 8;
    int z  = blockIdx.z;
    int kv = z & 1, b = (z >> 1) & 1, vi = z >> 2;
    const float* w    = kv ? vw : kw;
    const float* bias = kv ? vb : kb;

    __shared__ float sW[8][C];
    for (int idx = threadIdx.x; idx < 8 * C; idx += 256)
        sW[idx >> 7][idx & 127] = w[(o0 + (idx >> 7)) * C + (idx & 127)];
    __syncthreads();

    float acc[8];
#pragma unroll
    for (int oo = 0; oo < 8; oo++) acc[oo] = bias[o0 + oo];

    const float* xs = &g_xs[vi][b][0][0];
    for (int c = 0; c < C; c++) {
        float xv = xs[c * NS + n];
#pragma unroll
        for (int oo = 0; oo < 8; oo++) acc[oo] += sW[oo][c] * xv;
    }
    float* dst = kv ? &g_v[vi][b][0][0] : &g_k[vi][b][0][0];
#pragma unroll
    for (int oo = 0; oo < 8; oo++) dst[(o0 + oo) * NS + n] = acc[oo];
}

// =====================================================================
// Kernel 4: attention. R10 structure + (a) overlapping fp16-pair rpe
// window (one LDS.32 per bilinear row, taps (cx,cx+1) packed), and
// (b) direct-exp softmax (logits bounded -> no online max, no divergent
// rescale branch, no final max reduction).
// =====================================================================
__global__ __launch_bounds__(256, 2) void k_attn(
    const float* __restrict__ query,
    const float* __restrict__ rpe_table)
{
    int warp = threadIdx.x >> 5, lane = threadIdx.x & 31, tid = threadIdx.x;
    int vi = blockIdx.z;
    int bh = blockIdx.y;
    int b = bh / NH, h = bh % NH;
    int g = h / HPG;
    int bg = b * G + g;

    int mp = blockIdx.x * 8 + warp;      // pair index 0..511
    int i0 = (mp >> 5) * 2;              // same for all warps in a block
    int j  = mp & 31;
    int m0 = i0 * 32 + j;
    int m1 = m0 + 32;

    // channel-pair interleaved: sK2[cp][n] = (K[2cp][n], K[2cp+1][n])
    __shared__ float2 sK2[CH / 2][256];
    __shared__ float2 sV2[CH / 2][256];
    __shared__ float sR0[256];
    __shared__ float sR1[256];
    // overlapping pairs: sRpe[r][c] = (v[c-XOFF], v[c-XOFF+1]), zero-padded
    __shared__ __half2 sRpe[RPR][RPW];

    int r_lo = i0 - 6;                   // may be negative; pad rows are zero

    const float* rpe = rpe_table + h * RH * RW;
    // fill zero-padded overlapping-pair rpe window once per block
    for (int rr = warp; rr < RPR; rr += 8) {
        int trow = r_lo + rr;
        bool rok = (trow >= 0) && (trow < RH);
        const float* src = rpe + trow * RW;
        for (int c = lane; c < RPW; c += 32) {
            int xg = c - XOFF;
            float v0 = (rok && xg >= 0 && xg < RW) ? src[xg] : 0.f;
            float v1 = (rok && xg + 1 >= 0 && xg + 1 < RW) ? src[xg + 1] : 0.f;
            sRpe[rr][c] = __floats2half2_rn(v0, v1);
        }
    }

    // q packed as channel pairs, pre-scaled by SCALE
    unsigned long long qp0[CH / 2], qp1[CH / 2];
#pragma unroll
    for (int cp = 0; cp < CH / 2; cp++) {
        float a0 = query[(b * C + h * CH + 2 * cp) * M + m0] * SCALE;
        float b0 = query[(b * C + h * CH + 2 * cp + 1) * M + m0] * SCALE;
        float a1 = query[(b * C + h * CH + 2 * cp) * M + m1] * SCALE;
        float b1v = query[(b * C + h * CH + 2 * cp + 1) * M + m1] * SCALE;
        PACK2(qp0[cp], a0, b0);
        PACK2(qp1[cp], a1, b1v);
    }

    const float* kbase = &g_k[vi][b][h * CH][0];
    const float* vbase = &g_v[vi][b][h * CH][0];

    float ll0 = 0.f, ll1 = 0.f;          // direct exp sums (no max tracking)
    unsigned long long ap0[CH / 2], ap1[CH / 2];
    unsigned long long zero2; { PACK2(zero2, 0.f, 0.f); }
#pragma unroll
    for (int cp = 0; cp < CH / 2; cp++) { ap0[cp] = zero2; ap1[cp] = zero2; }

    float ybase = 15.5f + (float)i0;
    float xbase = 63.5f + (127.0f / 31.0f) * (float)j;

    for (int t = 0; t < NS / 256; t++) {
        __syncthreads();
        // lane-contiguous vectorized interleaving fill (proven in R8/R10)
        for (int idx = tid; idx < (CH / 2) * 64; idx += 256) {
            int cp = idx >> 6, n4 = idx & 63;
            float4 ka = ((const float4*)(kbase + (2 * cp) * NS + t * 256))[n4];
            float4 kb4 = ((const float4*)(kbase + (2 * cp + 1) * NS + t * 256))[n4];
            ((float4*)&sK2[cp][0])[2 * n4]     = make_float4(ka.x, kb4.x, ka.y, kb4.y);
            ((float4*)&sK2[cp][0])[2 * n4 + 1] = make_float4(ka.z, kb4.z, ka.w, kb4.w);
            float4 va = ((const float4*)(vbase + (2 * cp) * NS + t * 256))[n4];
            float4 vb4 = ((const float4*)(vbase + (2 * cp + 1) * NS + t * 256))[n4];
            ((float4*)&sV2[cp][0])[2 * n4]     = make_float4(va.x, vb4.x, va.y, vb4.y);
            ((float4*)&sV2[cp][0])[2 * n4 + 1] = make_float4(va.z, vb4.z, va.w, vb4.w);
        }
        {
            float2 rv = ((const float2*)&g_rwo[vi][bg][t * 256][0])[tid];
            sR0[tid] = rv.x;
            sR1[tid] = rv.y;
        }
        __syncthreads();

#pragma unroll 1
        for (int ch = 0; ch < 8; ch++) {
            int nl = ch * 32 + lane;

            // QK via packed channel pairs
            const unsigned long long* kc = (const unsigned long long*)&sK2[0][nl];
            unsigned long long s0p = zero2, s1p = zero2;
#pragma unroll
            for (int cp = 0; cp < CH / 2; cp++) {
                unsigned long long kk = kc[cp * 256];
                FMA2(s0p, qp0[cp], kk, s0p);
                FMA2(s1p, qp1[cp], kk, s1p);
            }
            float s0a, s0b, s1a, s1b;
            UNPACK2(s0a, s0b, s0p);
            UNPACK2(s1a, s1b, s1p);
            float s0 = s0a + s0b, s1 = s1a + s1b;

            // --- bilinear rpe: one packed LDS.32 per row, taps (cx,cx+1) ---
            float r0v = sR0[nl], r1v = sR1[nl];
            float yp = ybase - 15.5f * r0v;
            float xp = xbase - 63.5f * r1v;
            float yf = floorf(yp), xf = floorf(xp);
            float fy = yp - yf, fx = xp - xf;
            int cy = (int)yf - r_lo;          // in [0, 42]
            int cx = (int)xf + XOFF;          // in-bounds by construction

            const __half2* rp = &sRpe[cy][cx];
            float2 f0 = __half22float2(rp[0]);
            float2 f1 = __half22float2(rp[RPW]);
            float2 f2 = __half22float2(rp[2 * RPW]);
            float rc0 = (1.f - fx) * f0.x + fx * f0.y;
            float rc1 = (1.f - fx) * f1.x + fx * f1.y;
            float rc2 = (1.f - fx) * f2.x + fx * f2.y;

            s0 += (1.f - fy) * rc0 + fy * rc1;
            s1 += (1.f - fy) * rc1 + fy * rc2;

            // --- direct exp (logits bounded; softmax shift-invariant) ---
            float p0 = __expf(s0);
            float p1 = __expf(s1);
            ll0 += p0;
            ll1 += p1;

            unsigned long long p0p, p1p;
            PACK2(p0p, p0, p0);
            PACK2(p1p, p1, p1);
            const unsigned long long* vc = (const unsigned long long*)&sV2[0][nl];
#pragma unroll
            for (int cp = 0; cp < CH / 2; cp++) {
                unsigned long long vvp = vc[cp * 256];
                FMA2(ap0[cp], p0p, vvp, ap0[cp]);
                FMA2(ap1[cp], p1p, vvp, ap1[cp]);
            }
        }
    }

    // cross-lane sum reductions (no max needed)
    float ls0 = ll0, ls1 = ll1;
#pragma unroll
    for (int o = 16; o; o >>= 1) {
        ls0 += __shfl_xor_sync(0xffffffffu, ls0, o);
        ls1 += __shfl_xor_sync(0xffffffffu, ls1, o);
    }
    float inv0 = 1.f / ls0, inv1 = 1.f / ls1;

#pragma unroll
    for (int cp = 0; cp < CH / 2; cp++) {
        float a0, b0, a1, b1v;
        UNPACK2(a0, b0, ap0[cp]);
        UNPACK2(a1, b1v, ap1[cp]);
#pragma unroll
        for (int q = 16; q; q >>= 1) {
            a0  += __shfl_xor_sync(0xffffffffu, a0,  q);
            b0  += __shfl_xor_sync(0xffffffffu, b0,  q);
            a1  += __shfl_xor_sync(0xffffffffu, a1,  q);
            b1v += __shfl_xor_sync(0xffffffffu, b1v, q);
        }
        if (lane == 0) {
            g_outcat[b][vi * C + h * CH + 2 * cp][m0]     = a0 * inv0;
            g_outcat[b][vi * C + h * CH + 2 * cp + 1][m0] = b0 * inv0;
            g_outcat[b][vi * C + h * CH + 2 * cp][m1]     = a1 * inv1;
            g_outcat[b][vi * C + h * CH + 2 * cp + 1][m1] = b1v * inv1;
        }
    }
}

// =====================================================================
// Kernel 5: output projection (unchanged)
// =====================================================================
__global__ __launch_bounds__(256) void k_out(
    const float* __restrict__ ow, const float* __restrict__ ob,
    float* __restrict__ out)
{
    int mm = blockIdx.x * 256 + threadIdx.x;
    int o0 = blockIdx.y * 8;
    int b  = blockIdx.z;

    __shared__ float sW[8][V * C];
    for (int idx = threadIdx.x; idx < 8 * V * C; idx += 256)
        sW[idx / (V * C)][idx % (V * C)] = ow[(o0 + idx / (V * C)) * (V * C) + (idx % (V * C))];
    __syncthreads();

    float acc[8];
#pragma unroll
    for (int oo = 0; oo < 8; oo++) acc[oo] = ob[o0 + oo];

    const float* src = &g_outcat[b][0][0];
    for (int c = 0; c < V * C; c++) {
        float xv = src[c * M + mm];
#pragma unroll
        for (int oo = 0; oo < 8; oo++) acc[oo] += sW[oo][c] * xv;
    }
#pragma unroll
    for (int oo = 0; oo < 8; oo++)
        out[(b * C + o0 + oo) * M + mm] = acc[oo];
}

// =====================================================================
extern "C" void kernel_launch(void* const* d_in, const int* in_sizes, int n_in,
                              void* d_out, int out_size)
{
    const float *x, *query, *refpts, *off_w1, *off_b1, *off_ln_g, *off_ln_b,
                *off_w2, *k_w, *k_b, *v_w, *v_b, *out_w, *out_b, *rpe;

    if (n_in >= 15 && in_sizes[0] == 3145728) {
        x        = (const float*)d_in[0];
        query    = (const float*)d_in[1];
        refpts   = (const float*)d_in[2];
        off_w1   = (const float*)d_in[3];
        off_b1   = (const float*)d_in[4];
        off_ln_g = (const float*)d_in[5];
        off_ln_b = (const float*)d_in[6];
        off_w2   = (const float*)d_in[7];
        k_w      = (const float*)d_in[8];
        k_b      = (const float*)d_in[9];
        v_w      = (const float*)d_in[10];
        v_b      = (const float*)d_in[11];
        out_w    = (const float*)d_in[12];
        out_b    = (const float*)d_in[13];
        rpe      = (const float*)d_in[14];
    } else {
        k_b      = (const float*)d_in[0];
        k_w      = (const float*)d_in[1];
        off_b1   = (const float*)d_in[2];
        off_ln_b = (const float*)d_in[3];
        off_ln_g = (const float*)d_in[4];
        off_w1   = (const float*)d_in[5];
        off_w2   = (const float*)d_in[6];
        out_b    = (const float*)d_in[7];
        out_w    = (const float*)d_in[8];
        query    = (const float*)d_in[9];
        refpts   = (const float*)d_in[10];
        rpe      = (const float*)d_in[11];
        v_b      = (const float*)d_in[12];
        v_w      = (const float*)d_in[13];
        x        = (const float*)d_in[14];
    }
    float* out = (float*)d_out;

    k_offset<<<dim3(M / 256, B * G, V), 256>>>(query, refpts, off_w1, off_b1,
                                               off_ln_g, off_ln_b, off_w2);
    k_sample<<<dim3(NS / 4, B * G, V), 256>>>(x);
    k_proj<<<dim3(NS / 256, C / 8, V * B * 2), 256>>>(k_w, k_b, v_w, v_b);
    k_attn<<<dim3(M / 2 / 8, B * NH, V), 256>>>(query, rpe);
    k_out<<<dim3(M / 256, C / 8, B), 256>>>(out_w, out_b, out);
}

// round 17
// speedup vs baseline: 2.1718x; 1.1421x over previous
#include <cuda_runtime.h>
#include <cuda_fp16.h>
#include <math.h>

// ---------------- problem constants ----------------
constexpr int B = 2, V = 3, G = 2, NH = 8, C = 128;
constexpr int CPG = C / G;       // 64
constexpr int CH  = C / NH;      // 16
constexpr int HPG = NH / G;      // 4
constexpr int Hq = 32, Wq = 32, M = Hq * Wq;   // 1024
constexpr int D = 4;
constexpr int Hk = Hq / 2, Wk = Wq * D;        // 16, 128
constexpr int NS = Hk * Wk;                    // 2048
constexpr int Hi = 64, Wi = 64;
constexpr int RH = Hq * 2 - 1;   // 63
constexpr int RW = Wq * D * 2 - 1; // 255
constexpr float SCALE = 0.25f;
constexpr float OFR = 5.0f;
constexpr float EPS = 1e-5f;
// full zero-padded rpe window per head: rows y in [-6,68] (75), cols x in [-3,258] (262)
constexpr int RPR = 75;
constexpr int RPW = 262;
constexpr int YOFF = 6;
constexpr int XOFF = 3;
constexpr int NSPLIT = 4;        // n-range splits for parallelism

// packed f32x2 helpers
#define FMA2(d, a, b, c) asm("fma.rn.f32x2 %0, %1, %2, %3;" : "=l"(d) : "l"(a), "l"(b), "l"(c))
#define PACK2(d, lo, hi) asm("mov.b64 %0, {%1, %2};"        : "=l"(d) : "f"(lo), "f"(hi))
#define UNPACK2(lo, hi, v) asm("mov.b64 {%0, %1}, %2;"      : "=f"(lo), "=f"(hi) : "l"(v))

// ---------------- scratch ----------------
__device__ float g_rwo[V][B * G][NS][2];
__device__ float g_xs[V][B][C][NS];
__device__ float g_k[V][B][C][NS];
__device__ float g_v[V][B][C][NS];
__device__ float g_outcat[B][V * C][M];
__device__ float g_pacc[V][B * NH][NSPLIT][M][CH];   // ~12.6 MB partial accumulators
__device__ float g_pll[V][B * NH][NSPLIT][M];        // partial exp-sums

// =====================================================================
// Kernel 1: offset net (unchanged — correct)
// =====================================================================
__global__ __launch_bounds__(256) void k_offset(
    const float* __restrict__ query,
    const float* __restrict__ refpts,
    const float* __restrict__ w1,
    const float* __restrict__ b1,
    const float* __restrict__ lng,
    const float* __restrict__ lnb,
    const float* __restrict__ w2)
{
    int pix = blockIdx.x * 256 + threadIdx.x;
    int bg = blockIdx.y, vi = blockIdx.z;
    int b = bg / G, g = bg % G;
    int y = pix >> 5, x = pix & 31;

    const float* W1 = w1 + vi * 256;
    const float* B1 = b1 + vi * 256;
    const float* LG = lng + vi * 256;
    const float* LB = lnb + vi * 256;
    const float* W2 = w2 + vi * 4 * 256;

    float s = 0.f, ss = 0.f;
    for (int c = 0; c < CPG; c++) {
        float qv = query[((b * C + g * CPG + c) * Hq + y) * Wq + x];
#pragma unroll
        for (int d = 0; d < 4; d++) {
            int cd = c * 4 + d;
            float hv = qv * W1[cd] + B1[cd];
            s += hv; ss += hv * hv;
        }
    }
    float mu  = s * (1.f / 256.f);
    float var = ss * (1.f / 256.f) - mu * mu;
    float rs  = rsqrtf(var + EPS);

    float po[4] = {0.f, 0.f, 0.f, 0.f};
    for (int c = 0; c < CPG; c++) {
        float qv = query[((b * C + g * CPG + c) * Hq + y) * Wq + x];
#pragma unroll
        for (int d = 0; d < 4; d++) {
            int cd = c * 4 + d;
            float hv = qv * W1[cd] + B1[cd];
            float hn = (hv - mu) * rs * LG[cd] + LB[cd];
            float ge = 0.5f * hn * (1.f + erff(hn * 0.70710678118654752f));
#pragma unroll
            for (int d2 = 0; d2 < 4; d2++)
                po[d2] += ge * W2[d2 * 256 + cd];
        }
    }

    int p = y & 1, hk = y >> 1;
    float scl = (p == 0) ? (OFR / (float)(Hk - 1)) : (OFR / (float)(Wk - 1));
#pragma unroll
    for (int d = 0; d < 4; d++) {
        int wk = x * 4 + d;
        float rv = refpts[(((b * V + vi) * Hk + hk) * Wk + wk) * 2 + (1 - p)];
        g_rwo[vi][bg][hk * Wk + wk][p] = tanhf(po[d]) * scl + rv;
    }
}

// =====================================================================
// Kernel 2: bilinear grid-sample of x (unchanged)
// =====================================================================
__global__ __launch_bounds__(256) void k_sample(const float* __restrict__ x)
{
    int cc = threadIdx.x & 63;
    int nsub = threadIdx.x >> 6;
    int n = blockIdx.x * 4 + nsub;
    int bg = blockIdx.y, vi = blockIdx.z;
    int b = bg / G, g = bg % G;

    float r0 = g_rwo[vi][bg][n][0];
    float r1 = g_rwo[vi][bg][n][1];
    float yp = (r0 + 1.f) * 0.5f * (float)(Hi - 1);
    float xp = (r1 + 1.f) * 0.5f * (float)(Wi - 1);
    float y0f = floorf(yp), x0f = floorf(xp);
    float fy = yp - y0f, fx = xp - x0f;
    int y0 = (int)y0f, x0 = (int)x0f;

    float wy0 = (y0     >= 0 && y0     <= Hi - 1) ? (1.f - fy) : 0.f;
    float wy1 = (y0 + 1 >= 0 && y0 + 1 <= Hi - 1) ? fy         : 0.f;
    float wx0 = (x0     >= 0 && x0     <= Wi - 1) ? (1.f - fx) : 0.f;
    float wx1 = (x0 + 1 >= 0 && x0 + 1 <= Wi - 1) ? fx         : 0.f;
    int iy0 = min(max(y0, 0), Hi - 1), iy1 = min(max(y0 + 1, 0), Hi - 1);
    int ix0 = min(max(x0, 0), Wi - 1), ix1 = min(max(x0 + 1, 0), Wi - 1);

    const float* img = x + (size_t)((b * V + vi) * C + g * CPG + cc) * (Hi * Wi);
    float val = wy0 * wx0 * img[iy0 * Wi + ix0]
              + wy0 * wx1 * img[iy0 * Wi + ix1]
              + wy1 * wx0 * img[iy1 * Wi + ix0]
              + wy1 * wx1 * img[iy1 * Wi + ix1];
    g_xs[vi][b][g * CPG + cc][n] = val;
}

// =====================================================================
// Kernel 3: K/V projection (unchanged)
// =====================================================================
__global__ __launch_bounds__(256) void k_proj(
    const float* __restrict__ kw, const float* __restrict__ kb,
    const float* __restrict__ vw, const float* __restrict__ vb)
{
    int n  = blockIdx.x * 256 + threadIdx.x;
    int o0 = blockIdx.y * 8;
    int z  = blockIdx.z;
    int kv = z & 1, b = (z >> 1) & 1, vi = z >> 2;
    const float* w    = kv ? vw : kw;
    const float* bias = kv ? vb : kb;

    __shared__ float sW[8][C];
    for (int idx = threadIdx.x; idx < 8 * C; idx += 256)
        sW[idx >> 7][idx & 127] = w[(o0 + (idx >> 7)) * C + (idx & 127)];
    __syncthreads();

    float acc[8];
#pragma unroll
    for (int oo = 0; oo < 8; oo++) acc[oo] = bias[o0 + oo];

    const float* xs = &g_xs[vi][b][0][0];
    for (int c = 0; c < C; c++) {
        float xv = xs[c * NS + n];
#pragma unroll
        for (int oo = 0; oo < 8; oo++) acc[oo] += sW[oo][c] * xv;
    }
    float* dst = kv ? &g_v[vi][b][0][0] : &g_k[vi][b][0][0];
#pragma unroll
    for (int oo = 0; oo < 8; oo++) dst[(o0 + oo) * NS + n] = acc[oo];
}

// =====================================================================
// Kernel 4: attention v3 — warp = one j column, lane = query row i.
// K/V smem reads are warp-broadcast (amortized over 32 queries); rpe rows
// are consecutive integers across lanes (conflict-free fp16 gathers);
// direct-exp softmax; no cross-lane reductions at all. n-range split 4
// ways across blocks; partials combined by k_comb.
// =====================================================================
__global__ __launch_bounds__(256, 3) void k_attn(
    const float* __restrict__ query,
    const float* __restrict__ rpe_table)
{
    int warp = threadIdx.x >> 5, lane = threadIdx.x & 31, tid = threadIdx.x;
    int vi = blockIdx.z;
    int bh = blockIdx.y;
    int b = bh / NH, h = bh % NH;
    int g = h / HPG;
    int bg = b * G + g;

    int jg = blockIdx.x & 3;             // j group (8 j per block)
    int sp = blockIdx.x >> 2;            // n split 0..3
    int j = jg * 8 + warp;
    int m = lane * 32 + j;               // this lane's query

    // ---- shared memory ----
    __shared__ __align__(16) unsigned char sMem[16384 + 16384 + 2048];
    float4 (*sK4)[4] = (float4(*)[4])sMem;                    // [256][4] = K[n][ch quads]
    float4 (*sV4)[4] = (float4(*)[4])(sMem + 16384);
    float2* sR       = (float2*)(sMem + 32768);
    __shared__ __half sRpeH[RPR][RPW];                        // ~39.3 KB zero-padded fp16

    // ---- fill rpe window (once per block) ----
    const float* rpe = rpe_table + h * RH * RW;
    for (int rr = warp; rr < RPR; rr += 8) {
        int ty = rr - YOFF;
        bool rok = (ty >= 0) && (ty < RH);
        const float* src = rpe + ty * RW;
        for (int c = lane; c < RPW; c += 32) {
            int xg = c - XOFF;
            sRpeH[rr][c] = __float2half((rok && xg >= 0 && xg < RW) ? src[xg] : 0.f);
        }
    }

    // ---- stage q through smem (coalesced LDG), overlay on sK region ----
    {
        float (*sQf)[32][8] = (float(*)[32][8])sMem;   // [c][i][jj]
        for (int idx = tid; idx < CH * 32 * 8; idx += 256) {
            int c = idx >> 8, rem = idx & 255;
            int i = rem >> 3, jj = rem & 7;
            sQf[c][i][jj] = query[(b * C + h * CH + c) * M + i * 32 + jg * 8 + jj] * SCALE;
        }
    }
    __syncthreads();

    unsigned long long qp[CH / 2];
    {
        float (*sQf)[32][8] = (float(*)[32][8])sMem;
#pragma unroll
        for (int cp = 0; cp < CH / 2; cp++) {
            float a = sQf[2 * cp][lane][warp];
            float bb = sQf[2 * cp + 1][lane][warp];
            PACK2(qp[cp], a, bb);
        }
    }

    const float* kbase = &g_k[vi][b][h * CH][0];
    const float* vbase = &g_v[vi][b][h * CH][0];

    float ll = 0.f;
    unsigned long long ap[CH / 2];
    unsigned long long zero2; { PACK2(zero2, 0.f, 0.f); }
#pragma unroll
    for (int cp = 0; cp < CH / 2; cp++) ap[cp] = zero2;

    // yp' = (15.5 + YOFF) - 15.5*r0 (+ lane later);  xp' = (63.5 + XOFF) + 4.0968*j - 63.5*r1
    float xbase = (63.5f + (float)XOFF) + (127.0f / 31.0f) * (float)j;
    float ycon  = 15.5f + (float)YOFF;

    for (int tt = 0; tt < NS / 256 / NSPLIT; tt++) {
        int t = sp * (NS / 256 / NSPLIT) + tt;
        __syncthreads();
        // fill K/V tiles transposed: thread = one n, 16 coalesced LDG + 4 STS.128
        {
            int n = tid;
            const float* kp = kbase + t * 256 + n;
            float a0 = kp[0], a1 = kp[NS], a2 = kp[2 * NS], a3 = kp[3 * NS];
            float a4 = kp[4 * NS], a5 = kp[5 * NS], a6 = kp[6 * NS], a7 = kp[7 * NS];
            float a8 = kp[8 * NS], a9 = kp[9 * NS], a10 = kp[10 * NS], a11 = kp[11 * NS];
            float a12 = kp[12 * NS], a13 = kp[13 * NS], a14 = kp[14 * NS], a15 = kp[15 * NS];
            sK4[n][0] = make_float4(a0, a1, a2, a3);
            sK4[n][1] = make_float4(a4, a5, a6, a7);
            sK4[n][2] = make_float4(a8, a9, a10, a11);
            sK4[n][3] = make_float4(a12, a13, a14, a15);
            const float* vp = vbase + t * 256 + n;
            a0 = vp[0]; a1 = vp[NS]; a2 = vp[2 * NS]; a3 = vp[3 * NS];
            a4 = vp[4 * NS]; a5 = vp[5 * NS]; a6 = vp[6 * NS]; a7 = vp[7 * NS];
            a8 = vp[8 * NS]; a9 = vp[9 * NS]; a10 = vp[10 * NS]; a11 = vp[11 * NS];
            a12 = vp[12 * NS]; a13 = vp[13 * NS]; a14 = vp[14 * NS]; a15 = vp[15 * NS];
            sV4[n][0] = make_float4(a0, a1, a2, a3);
            sV4[n][1] = make_float4(a4, a5, a6, a7);
            sV4[n][2] = make_float4(a8, a9, a10, a11);
            sV4[n][3] = make_float4(a12, a13, a14, a15);
            sR[n] = ((const float2*)&g_rwo[vi][bg][t * 256][0])[n];
        }
        __syncthreads();

#pragma unroll 1
        for (int n = 0; n < 256; n++) {
            // broadcast K (4x LDS.128)
            float4 kA = sK4[n][0], kB = sK4[n][1], kC = sK4[n][2], kD = sK4[n][3];
            const unsigned long long* kpq;

            unsigned long long sE = zero2, sO = zero2;
            kpq = (const unsigned long long*)&kA;
            FMA2(sE, qp[0], kpq[0], sE);
            FMA2(sO, qp[1], kpq[1], sO);
            kpq = (const unsigned long long*)&kB;
            FMA2(sE, qp[2], kpq[0], sE);
            FMA2(sO, qp[3], kpq[1], sO);
            kpq = (const unsigned long long*)&kC;
            FMA2(sE, qp[4], kpq[0], sE);
            FMA2(sO, qp[5], kpq[1], sO);
            kpq = (const unsigned long long*)&kD;
            FMA2(sE, qp[6], kpq[0], sE);
            FMA2(sO, qp[7], kpq[1], sO);
            float e0, e1, o0, o1;
            UNPACK2(e0, e1, sE);
            UNPACK2(o0, o1, sO);
            float s = (e0 + e1) + (o0 + o1);

            // bias: rows consecutive across lanes, fy lane-invariant
            float2 rv = sR[n];                  // broadcast LDS.64
            float ypc = ycon - 15.5f * rv.x;    // + lane gives this lane's yp
            float xp = xbase - 63.5f * rv.y;
            float yf = floorf(ypc);
            float xf = floorf(xp);
            float fy = ypc - yf;
            float fx = xp - xf;
            int ry = (int)yf + lane;            // row in window, in [0, 73]
            int cx = (int)xf;                   // col in window

            const __half* rp = &sRpeH[ry][cx];
            float lo0 = __half2float(rp[0]),   hi0 = __half2float(rp[1]);
            float lo1 = __half2float(rp[RPW]), hi1 = __half2float(rp[RPW + 1]);
            float rc0 = (1.f - fx) * lo0 + fx * hi0;
            float rc1 = (1.f - fx) * lo1 + fx * hi1;
            s += (1.f - fy) * rc0 + fy * rc1;

            // direct exp (softmax shift-invariant; logits bounded)
            float p = __expf(s);
            ll += p;
            unsigned long long pp;
            PACK2(pp, p, p);

            // broadcast V (4x LDS.128) + PV
            float4 vA = sV4[n][0], vB = sV4[n][1], vC = sV4[n][2], vD = sV4[n][3];
            const unsigned long long* vpq;
            vpq = (const unsigned long long*)&vA;
            FMA2(ap[0], pp, vpq[0], ap[0]);
            FMA2(ap[1], pp, vpq[1], ap[1]);
            vpq = (const unsigned long long*)&vB;
            FMA2(ap[2], pp, vpq[0], ap[2]);
            FMA2(ap[3], pp, vpq[1], ap[3]);
            vpq = (const unsigned long long*)&vC;
            FMA2(ap[4], pp, vpq[0], ap[4]);
            FMA2(ap[5], pp, vpq[1], ap[5]);
            vpq = (const unsigned long long*)&vD;
            FMA2(ap[6], pp, vpq[0], ap[6]);
            FMA2(ap[7], pp, vpq[1], ap[7]);
        }
    }

    // write partials (no cross-lane reduction needed — lane owns query m)
    g_pll[vi][bh][sp][m] = ll;
    float* pa = &g_pacc[vi][bh][sp][m][0];
#pragma unroll
    for (int cp2 = 0; cp2 < 4; cp2++) {
        float a0, a1, a2, a3;
        UNPACK2(a0, a1, ap[2 * cp2]);
        UNPACK2(a2, a3, ap[2 * cp2 + 1]);
        ((float4*)pa)[cp2] = make_float4(a0, a1, a2, a3);
    }
}

// =====================================================================
// Kernel 4b: combine split partials -> g_outcat
// =====================================================================
__global__ __launch_bounds__(256) void k_comb()
{
    int gid = blockIdx.x * 256 + threadIdx.x;    // 49152 query-slots
    int m = gid & 1023;
    int bh = (gid >> 10) & 15;
    int vi = gid >> 14;
    int b = bh / NH, h = bh % NH;

    float ll = 0.f;
#pragma unroll
    for (int s = 0; s < NSPLIT; s++) ll += g_pll[vi][bh][s][m];
    float inv = 1.f / ll;

    float4 o[4] = {make_float4(0, 0, 0, 0), make_float4(0, 0, 0, 0),
                   make_float4(0, 0, 0, 0), make_float4(0, 0, 0, 0)};
#pragma unroll
    for (int s = 0; s < NSPLIT; s++) {
        const float4* p = (const float4*)&g_pacc[vi][bh][s][m][0];
#pragma unroll
        for (int q4 = 0; q4 < 4; q4++) {
            float4 v = p[q4];
            o[q4].x += v.x; o[q4].y += v.y; o[q4].z += v.z; o[q4].w += v.w;
        }
    }
    const float* of = (const float*)o;
#pragma unroll
    for (int c = 0; c < CH; c++)
        g_outcat[b][vi * C + h * CH + c][m] = of[c] * inv;
}

// =====================================================================
// Kernel 5: output projection (unchanged)
// =====================================================================
__global__ __launch_bounds__(256) void k_out(
    const float* __restrict__ ow, const float* __restrict__ ob,
    float* __restrict__ out)
{
    int mm = blockIdx.x * 256 + threadIdx.x;
    int o0 = blockIdx.y * 8;
    int b  = blockIdx.z;

    __shared__ float sW[8][V * C];
    for (int idx = threadIdx.x; idx < 8 * V * C; idx += 256)
        sW[idx / (V * C)][idx % (V * C)] = ow[(o0 + idx / (V * C)) * (V * C) + (idx % (V * C))];
    __syncthreads();

    float acc[8];
#pragma unroll
    for (int oo = 0; oo < 8; oo++) acc[oo] = ob[o0 + oo];

    const float* src = &g_outcat[b][0][0];
    for (int c = 0; c < V * C; c++) {
        float xv = src[c * M + mm];
#pragma unroll
        for (int oo = 0; oo < 8; oo++) acc[oo] += sW[oo][c] * xv;
    }
#pragma unroll
    for (int oo = 0; oo < 8; oo++)
        out[(b * C + o0 + oo) * M + mm] = acc[oo];
}

// =====================================================================
extern "C" void kernel_launch(void* const* d_in, const int* in_sizes, int n_in,
                              void* d_out, int out_size)
{
    const float *x, *query, *refpts, *off_w1, *off_b1, *off_ln_g, *off_ln_b,
                *off_w2, *k_w, *k_b, *v_w, *v_b, *out_w, *out_b, *rpe;

    if (n_in >= 15 && in_sizes[0] == 3145728) {
        x        = (const float*)d_in[0];
        query    = (const float*)d_in[1];
        refpts   = (const float*)d_in[2];
        off_w1   = (const float*)d_in[3];
        off_b1   = (const float*)d_in[4];
        off_ln_g = (const float*)d_in[5];
        off_ln_b = (const float*)d_in[6];
        off_w2   = (const float*)d_in[7];
        k_w      = (const float*)d_in[8];
        k_b      = (const float*)d_in[9];
        v_w      = (const float*)d_in[10];
        v_b      = (const float*)d_in[11];
        out_w    = (const float*)d_in[12];
        out_b    = (const float*)d_in[13];
        rpe      = (const float*)d_in[14];
    } else {
        k_b      = (const float*)d_in[0];
        k_w      = (const float*)d_in[1];
        off_b1   = (const float*)d_in[2];
        off_ln_b = (const float*)d_in[3];
        off_ln_g = (const float*)d_in[4];
        off_w1   = (const float*)d_in[5];
        off_w2   = (const float*)d_in[6];
        out_b    = (const float*)d_in[7];
        out_w    = (const float*)d_in[8];
        query    = (const float*)d_in[9];
        refpts   = (const float*)d_in[10];
        rpe      = (const float*)d_in[11];
        v_b      = (const float*)d_in[12];
        v_w      = (const float*)d_in[13];
        x        = (const float*)d_in[14];
    }
    float* out = (float*)d_out;

    k_offset<<<dim3(M / 256, B * G, V), 256>>>(query, refpts, off_w1, off_b1,
                                               off_ln_g, off_ln_b, off_w2);
    k_sample<<<dim3(NS / 4, B * G, V), 256>>>(x);
    k_proj<<<dim3(NS / 256, C / 8, V * B * 2), 256>>>(k_w, k_b, v_w, v_b);
    k_attn<<<dim3(4 * NSPLIT, B * NH, V), 256>>>(query, rpe);
    k_comb<<<dim3(V * B * NH * M / 256, 1, 1), 256>>>();
    k_out<<<dim3(M / 256, C / 8, B), 256>>>(out_w, out_b, out);
}